// round 7
// baseline (speedup 1.0000x reference)
#include <cuda_runtime.h>
#include <cuda_bf16.h>
#include <cstdint>

#define DEVINL __device__ __forceinline__

static constexpr int NN = 16384;   // nodes
static constexpr int DF = 256;     // feature dim == out dim
static constexpr int K2 = 1024;    // GEMM2 K: [f_hi | f_hi | f_lo | neigh]

// ---------------- scratch (device globals; no allocation allowed) -----------
__device__ __align__(128) __nv_bfloat16 g_fT[(size_t)DF * NN];   // 8 MB  features^T bf16
__device__ __align__(128) __nv_bfloat16 g_A2[(size_t)NN * K2];   // 32 MB GEMM2 A operand
__device__ __align__(128) __nv_bfloat16 g_B2[(size_t)DF * K2];   // 512 KB GEMM2 B operand

// ---------------- PTX helpers (all legal at compute_103 virtual arch) -------
DEVINL uint32_t smem_u32(const void* p) {
    uint32_t a;
    asm("{ .reg .u64 t; cvta.to.shared.u64 t, %1; cvt.u32.u64 %0, t; }"
        : "=r"(a) : "l"(p));
    return a;
}
DEVINL void cp16(uint32_t dst, const void* src) {
    asm volatile("cp.async.cg.shared.global [%0], [%1], 16;"
                 :: "r"(dst), "l"(src) : "memory");
}
DEVINL void cp_commit() { asm volatile("cp.async.commit_group;" ::: "memory"); }
template <int N> DEVINL void cp_wait() {
    asm volatile("cp.async.wait_group %0;" :: "n"(N) : "memory");
}
DEVINL void ldsm4(uint32_t* r, uint32_t a) {
    asm volatile("ldmatrix.sync.aligned.m8n8.x4.shared.b16 {%0,%1,%2,%3}, [%4];"
                 : "=r"(r[0]), "=r"(r[1]), "=r"(r[2]), "=r"(r[3]) : "r"(a));
}
DEVINL void sts128(uint32_t a, uint32_t x, uint32_t y, uint32_t z, uint32_t w) {
    asm volatile("st.shared.v4.b32 [%0], {%1,%2,%3,%4};"
                 :: "r"(a), "r"(x), "r"(y), "r"(z), "r"(w));
}
DEVINL void mma16816(float* d, const uint32_t* a, uint32_t b0, uint32_t b1) {
    asm volatile(
        "mma.sync.aligned.m16n8k16.row.col.f32.bf16.bf16.f32 "
        "{%0,%1,%2,%3}, {%4,%5,%6,%7}, {%8,%9}, {%0,%1,%2,%3};"
        : "+f"(d[0]), "+f"(d[1]), "+f"(d[2]), "+f"(d[3])
        : "r"(a[0]), "r"(a[1]), "r"(a[2]), "r"(a[3]), "r"(b0), "r"(b1));
}
DEVINL uint32_t packbf2(float x, float y) {
    __nv_bfloat162 h = __floats2bfloat162_rn(x, y);
    return *reinterpret_cast<uint32_t*>(&h);
}
DEVINL float4 ldcs4(const float* p) {
    float4 v;
    asm volatile("ld.global.cs.v4.f32 {%0,%1,%2,%3}, [%4];"
                 : "=f"(v.x), "=f"(v.y), "=f"(v.z), "=f"(v.w) : "l"(p));
    return v;
}

// ---------------- prep kernels ----------------------------------------------

// features^T (bf16) via tiled transpose. grid(512, 8), block(32, 8)
__global__ void prep_fT(const float* __restrict__ f) {
    __shared__ __nv_bfloat16 tile[32][33];
    const int i0 = blockIdx.x * 32, d0 = blockIdx.y * 32;
    const int tx = threadIdx.x, ty = threadIdx.y;
#pragma unroll
    for (int k = 0; k < 32; k += 8)
        tile[ty + k][tx] = __float2bfloat16(f[(size_t)(i0 + ty + k) * DF + d0 + tx]);
    __syncthreads();
#pragma unroll
    for (int k = 0; k < 32; k += 8)
        g_fT[(size_t)(d0 + ty + k) * NN + i0 + tx] = tile[tx][ty + k];
}

// A2 = [f_hi | f_hi | f_lo | (neigh filled by GEMM1 epilogue)]
__global__ void __launch_bounds__(256) prep_A2(const float* __restrict__ f) {
    const int i = blockIdx.x, d = threadIdx.x;
    const float v = f[(size_t)i * DF + d];
    const __nv_bfloat16 h = __float2bfloat16(v);
    const size_t b = (size_t)i * K2;
    g_A2[b + d]       = h;
    g_A2[b + 256 + d] = h;
    g_A2[b + 512 + d] = __float2bfloat16(v - __bfloat162float(h));
}

// B2 = [W1_hi | W1_lo | W1_hi | W2]
__global__ void __launch_bounds__(256) prep_W(const float* __restrict__ W) {
    const int o = blockIdx.x, c = threadIdx.x;
    const float w1 = W[(size_t)o * 512 + c];
    const __nv_bfloat16 h = __float2bfloat16(w1);
    const size_t b = (size_t)o * K2;
    g_B2[b + c]       = h;
    g_B2[b + 256 + c] = __float2bfloat16(w1 - __bfloat162float(h));
    g_B2[b + 512 + c] = h;
    g_B2[b + 768 + c] = __float2bfloat16(W[(size_t)o * 512 + 256 + c]);
}

// ---------------- mma.sync GEMM ----------------------------------------------
// Block tile 128x256, BK=64, 512 threads = 16 warps (4 M x 4 N), warp tile 32x64.
// SW128-style swizzle. B: 4-stage cp.async pipeline, per-tile commit groups,
// wait_group<2> (3 tiles of prefetch slack). A (mode1): 2-stage LDG->STS.
static constexpr int BM = 128, BN = 256, BK = 64;
static constexpr int ABYTES = BM * BK * 2;        // 16 KB / stage
static constexpr int BBYTES = BN * BK * 2;        // 32 KB / stage
static constexpr int BSTAGES = 4;

// MODE 1: C = bf16(adj_f32) @ fT^T; fused row-sum -> inv_deg; epilogue scales,
//         writes bf16 neigh into g_A2[:, 768:1024].
// MODE 2: C = A2 @ B2^T (K=1024 hi/lo split); epilogue writes fp32 out.
template <int MODE>
__global__ void __launch_bounds__(512, 1)
gemm_mma(float* __restrict__ outF, const float* __restrict__ adjF) {
    constexpr int  KT      = (MODE == 1) ? (NN / BK) : (K2 / BK);
    constexpr long ldb     = (MODE == 1) ? NN : K2;
    constexpr int  ASTAGES = (MODE == 1) ? 2 : 4;
    constexpr uint32_t A_OFF = 0;
    constexpr uint32_t B_OFF = ASTAGES * ABYTES;
    const __nv_bfloat16* __restrict__ Bg = (MODE == 1) ? g_fT : g_B2;

    extern __shared__ char smraw[];
    __shared__ float sdeg[BM];
    const uint32_t sb = (smem_u32(smraw) + 127u) & ~127u;

    const int tid  = threadIdx.x;
    const int lane = tid & 31;
    const int w    = tid >> 5;
    const int wm   = w >> 2;            // 0..3  (M dir)
    const int wn   = w & 3;             // 0..3  (N dir)
    const long m0  = (long)blockIdx.x * BM;

    float acc[2][8][4];
#pragma unroll
    for (int i = 0; i < 2; i++)
#pragma unroll
        for (int j = 0; j < 8; j++)
#pragma unroll
            for (int k = 0; k < 4; k++) acc[i][j][k] = 0.f;

    // --- B tile loader (cp.async, bf16, swizzled) ---
    auto cpB = [&](int s, int kt) {
        const long k0 = (long)kt * BK;
        const uint32_t base = sb + B_OFF + (uint32_t)s * BBYTES;
#pragma unroll
        for (int t = 0; t < 4; t++) {                 // 256 rows x 8 chunks(16B)
            const int idx = tid + t * 512;
            const int row = idx >> 3, c = idx & 7;
            const uint32_t off = (uint32_t)row * 128u +
                                 ((uint32_t)(c ^ (row & 7)) << 4);
            cp16(base + off, Bg + (long)row * ldb + k0 + c * 8);
        }
    };
    // --- A tile loader, MODE2 (bf16 g_A2 via cp.async) ---
    auto cpA2 = [&](int s, int kt) {
        const long k0 = (long)kt * BK;
        const uint32_t base = sb + A_OFF + (uint32_t)s * ABYTES;
#pragma unroll
        for (int t = 0; t < 2; t++) {                 // 128 rows x 8 chunks
            const int idx = tid + t * 512;
            const int row = idx >> 3, c = idx & 7;
            const uint32_t off = (uint32_t)row * 128u +
                                 ((uint32_t)(c ^ (row & 7)) << 4);
            cp16(base + off, g_A2 + (m0 + row) * (long)K2 + k0 + c * 8);
        }
    };

    // --- A tile register staging, MODE1 (f32 adj streaming LDG + row-sum) ---
    float4 rA[4];
    float  rowsum = 0.f;
    const int arow = tid >> 2;          // 0..127: row within tile
    const int aq   = tid & 3;           // quarter: cols aq*16 .. aq*16+15
    auto ldgA = [&](int kt) {
        const float* src = adjF + (m0 + arow) * (long)NN + (long)kt * BK + aq * 16;
#pragma unroll
        for (int j = 0; j < 4; j++) rA[j] = ldcs4(src + j * 4);
#pragma unroll
        for (int j = 0; j < 4; j++)
            rowsum += (rA[j].x + rA[j].y) + (rA[j].z + rA[j].w);
    };
    auto stsA = [&](int s) {
        const uint32_t base = sb + A_OFF + (uint32_t)s * ABYTES + (uint32_t)arow * 128u;
        const int rs = arow & 7;
#pragma unroll
        for (int j = 0; j < 2; j++) {
            const uint32_t p0 = packbf2(rA[2 * j].x, rA[2 * j].y);
            const uint32_t p1 = packbf2(rA[2 * j].z, rA[2 * j].w);
            const uint32_t p2 = packbf2(rA[2 * j + 1].x, rA[2 * j + 1].y);
            const uint32_t p3 = packbf2(rA[2 * j + 1].z, rA[2 * j + 1].w);
            sts128(base + ((uint32_t)((aq * 2 + j) ^ rs) << 4), p0, p1, p2, p3);
        }
    };

    // --- ldmatrix thread addressing (canonical m16n8k16 recipe) ---
    const int lhi  = lane >> 4;                       // k-chunk parity
    const int a_r0 = wm * 32 + (lane & 15);           // + mi*16
    const int b_r0 = wn * 64 + (lane & 15);           // + nb*16

    auto compute = [&](int sa, int sbg) {
        const uint32_t aBase = sb + A_OFF + (uint32_t)sa * ABYTES;
        const uint32_t bBase = sb + B_OFF + (uint32_t)sbg * BBYTES;
#pragma unroll
        for (int ks = 0; ks < 4; ks++) {              // 4 x k16 per BK=64
            uint32_t af[2][4], bf[4][4];
#pragma unroll
            for (int mi = 0; mi < 2; mi++) {
                const int row = a_r0 + mi * 16;
                const uint32_t addr = aBase + (uint32_t)row * 128u +
                    ((uint32_t)((ks * 2 + lhi) ^ (row & 7)) << 4);
                ldsm4(af[mi], addr);
            }
#pragma unroll
            for (int nb = 0; nb < 4; nb++) {
                const int row = b_r0 + nb * 16;
                const uint32_t addr = bBase + (uint32_t)row * 128u +
                    ((uint32_t)((ks * 2 + lhi) ^ (row & 7)) << 4);
                ldsm4(bf[nb], addr);
            }
#pragma unroll
            for (int mi = 0; mi < 2; mi++)
#pragma unroll
                for (int nb = 0; nb < 4; nb++) {
                    mma16816(acc[mi][nb * 2],     af[mi], bf[nb][0], bf[nb][2]);
                    mma16816(acc[mi][nb * 2 + 1], af[mi], bf[nb][1], bf[nb][3]);
                }
        }
    };

    // ---------------- prologue: commit B groups for tiles 0,1,2 -------------
    if constexpr (MODE == 1) {
        ldgA(0); stsA(0);               // tile 0 A into stage 0
        ldgA(1);                        // tile 1 A staged in regs
        cpB(0, 0); cp_commit();
        cpB(1, 1); cp_commit();
        cpB(2, 2); cp_commit();
    } else {
        cpA2(0, 0); cpB(0, 0); cp_commit();
        cpA2(1, 1); cpB(1, 1); cp_commit();
        cpA2(2, 2); cpB(2, 2); cp_commit();
    }

    // ---------------- main loop ----------------
    // Invariant at top of iter kt: committed groups = tiles {kt, kt+1, kt+2}.
    // wait_group<2> -> tile kt's group complete, 2 newer still in flight.
    // The syncthreads additionally proves all warps finished compute(kt-1),
    // so stage (kt-1)%4 == (kt+3)%4 is read-idle before we refill it.
    for (int kt = 0; kt < KT; kt++) {
        cp_wait<2>();
        __syncthreads();
        if (kt + 3 < KT) {
            const int sn = (kt + 3) & (BSTAGES - 1);
            if constexpr (MODE == 2) cpA2(sn, kt + 3);
            cpB(sn, kt + 3);
        }
        cp_commit();                    // exactly one group per iteration
        if constexpr (MODE == 1) {
            if (kt + 1 < KT) stsA((kt + 1) & 1);   // rA holds tile kt+1
            if (kt + 2 < KT) ldgA(kt + 2);
        }
        compute((MODE == 1) ? (kt & 1) : (kt & 3), kt & (BSTAGES - 1));
    }

    // ---------------- epilogue ----------------
    if constexpr (MODE == 1) {
        rowsum += __shfl_xor_sync(0xFFFFFFFFu, rowsum, 1);
        rowsum += __shfl_xor_sync(0xFFFFFFFFu, rowsum, 2);
        if ((tid & 3) == 0) sdeg[tid >> 2] = 1.0f / (rowsum + 1.0f);
        __syncthreads();
    }

#pragma unroll
    for (int mi = 0; mi < 2; mi++) {
        const int rl = wm * 32 + mi * 16 + (lane >> 2);
        const float slo = (MODE == 1) ? sdeg[rl]     : 1.f;
        const float shi = (MODE == 1) ? sdeg[rl + 8] : 1.f;
        const long glo = m0 + rl, ghi = glo + 8;
#pragma unroll
        for (int ni = 0; ni < 8; ni++) {
            const int col = wn * 64 + ni * 8 + (lane & 3) * 2;
            const float* a = acc[mi][ni];
            if constexpr (MODE == 1) {
                *reinterpret_cast<uint32_t*>(g_A2 + glo * K2 + 768 + col) =
                    packbf2(a[0] * slo, a[1] * slo);
                *reinterpret_cast<uint32_t*>(g_A2 + ghi * K2 + 768 + col) =
                    packbf2(a[2] * shi, a[3] * shi);
            } else {
                *reinterpret_cast<float2*>(outF + glo * DF + col) =
                    make_float2(a[0], a[1]);
                *reinterpret_cast<float2*>(outF + ghi * DF + col) =
                    make_float2(a[2], a[3]);
            }
        }
    }
}

static constexpr uint32_t SMEM1 = 2 * ABYTES + BSTAGES * BBYTES + 128;  // ~160 KB
static constexpr uint32_t SMEM2 = 4 * ABYTES + BSTAGES * BBYTES + 128;  // ~192 KB

// ---------------- launch -----------------------------------------------------
extern "C" void kernel_launch(void* const* d_in, const int* in_sizes, int n_in,
                              void* d_out, int out_size) {
    const float* features = nullptr;
    const float* adj      = nullptr;
    const float* W        = nullptr;
    for (int i = 0; i < n_in; i++) {
        if (in_sizes[i] == NN * DF)          features = (const float*)d_in[i];
        else if (in_sizes[i] == DF * 2 * DF) W        = (const float*)d_in[i];
        else                                  adj      = (const float*)d_in[i];
    }

    cudaFuncSetAttribute(gemm_mma<1>, cudaFuncAttributeMaxDynamicSharedMemorySize, SMEM1);
    cudaFuncSetAttribute(gemm_mma<2>, cudaFuncAttributeMaxDynamicSharedMemorySize, SMEM2);

    prep_fT<<<dim3(NN / 32, DF / 32), dim3(32, 8)>>>(features);
    prep_A2<<<NN, 256>>>(features);
    prep_W<<<DF, 256>>>(W);
    gemm_mma<1><<<NN / BM, 512, SMEM1>>>(nullptr, adj);
    gemm_mma<2><<<NN / BM, 512, SMEM2>>>((float*)d_out, nullptr);
}

// round 8
// speedup vs baseline: 1.1504x; 1.1504x over previous
#include <cuda_runtime.h>
#include <cuda_bf16.h>
#include <cstdint>

#define DEVINL __device__ __forceinline__

static constexpr int NN = 16384;   // nodes
static constexpr int DF = 256;     // feature dim == out dim
static constexpr int K2 = 1024;    // GEMM2 K: [f_hi | f_hi | f_lo | neigh]

// ---------------- scratch (device globals; no allocation allowed) -----------
__device__ __align__(128) __nv_bfloat16 g_fT[(size_t)DF * NN];   // 8 MB  features^T bf16
__device__ __align__(128) __nv_bfloat16 g_A2[(size_t)NN * K2];   // 32 MB GEMM2 A operand
__device__ __align__(128) __nv_bfloat16 g_B2[(size_t)DF * K2];   // 512 KB GEMM2 B operand

// ---------------- PTX helpers (all legal at compute_103 virtual arch) -------
DEVINL uint32_t smem_u32(const void* p) {
    uint32_t a;
    asm("{ .reg .u64 t; cvta.to.shared.u64 t, %1; cvt.u32.u64 %0, t; }"
        : "=r"(a) : "l"(p));
    return a;
}
DEVINL void cp16(uint32_t dst, const void* src) {
    asm volatile("cp.async.cg.shared.global [%0], [%1], 16;"
                 :: "r"(dst), "l"(src) : "memory");
}
DEVINL void cp_commit() { asm volatile("cp.async.commit_group;" ::: "memory"); }
template <int N> DEVINL void cp_wait() {
    asm volatile("cp.async.wait_group %0;" :: "n"(N) : "memory");
}
DEVINL void ldsm4(uint32_t* r, uint32_t a) {
    asm volatile("ldmatrix.sync.aligned.m8n8.x4.shared.b16 {%0,%1,%2,%3}, [%4];"
                 : "=r"(r[0]), "=r"(r[1]), "=r"(r[2]), "=r"(r[3]) : "r"(a));
}
DEVINL void sts128(uint32_t a, uint32_t x, uint32_t y, uint32_t z, uint32_t w) {
    asm volatile("st.shared.v4.b32 [%0], {%1,%2,%3,%4};"
                 :: "r"(a), "r"(x), "r"(y), "r"(z), "r"(w));
}
DEVINL void mma16816(float* d, const uint32_t* a, uint32_t b0, uint32_t b1) {
    asm volatile(
        "mma.sync.aligned.m16n8k16.row.col.f32.bf16.bf16.f32 "
        "{%0,%1,%2,%3}, {%4,%5,%6,%7}, {%8,%9}, {%0,%1,%2,%3};"
        : "+f"(d[0]), "+f"(d[1]), "+f"(d[2]), "+f"(d[3])
        : "r"(a[0]), "r"(a[1]), "r"(a[2]), "r"(a[3]), "r"(b0), "r"(b1));
}
DEVINL uint32_t packbf2(float x, float y) {
    __nv_bfloat162 h = __floats2bfloat162_rn(x, y);
    return *reinterpret_cast<uint32_t*>(&h);
}
DEVINL float4 ldcs4(const float* p) {
    float4 v;
    asm volatile("ld.global.cs.v4.f32 {%0,%1,%2,%3}, [%4];"
                 : "=f"(v.x), "=f"(v.y), "=f"(v.z), "=f"(v.w) : "l"(p));
    return v;
}

// ---------------- prep kernels ----------------------------------------------

// features^T (bf16) via tiled transpose. grid(512, 8), block(32, 8)
__global__ void prep_fT(const float* __restrict__ f) {
    __shared__ __nv_bfloat16 tile[32][33];
    const int i0 = blockIdx.x * 32, d0 = blockIdx.y * 32;
    const int tx = threadIdx.x, ty = threadIdx.y;
#pragma unroll
    for (int k = 0; k < 32; k += 8)
        tile[ty + k][tx] = __float2bfloat16(f[(size_t)(i0 + ty + k) * DF + d0 + tx]);
    __syncthreads();
#pragma unroll
    for (int k = 0; k < 32; k += 8)
        g_fT[(size_t)(d0 + ty + k) * NN + i0 + tx] = tile[tx][ty + k];
}

// A2 = [f_hi | f_hi | f_lo | (neigh filled by GEMM1 epilogue)]
__global__ void __launch_bounds__(256) prep_A2(const float* __restrict__ f) {
    const int i = blockIdx.x, d = threadIdx.x;
    const float v = f[(size_t)i * DF + d];
    const __nv_bfloat16 h = __float2bfloat16(v);
    const size_t b = (size_t)i * K2;
    g_A2[b + d]       = h;
    g_A2[b + 256 + d] = h;
    g_A2[b + 512 + d] = __float2bfloat16(v - __bfloat162float(h));
}

// B2 = [W1_hi | W1_lo | W1_hi | W2]
__global__ void __launch_bounds__(256) prep_W(const float* __restrict__ W) {
    const int o = blockIdx.x, c = threadIdx.x;
    const float w1 = W[(size_t)o * 512 + c];
    const __nv_bfloat16 h = __float2bfloat16(w1);
    const size_t b = (size_t)o * K2;
    g_B2[b + c]       = h;
    g_B2[b + 256 + c] = __float2bfloat16(w1 - __bfloat162float(h));
    g_B2[b + 512 + c] = h;
    g_B2[b + 768 + c] = __float2bfloat16(W[(size_t)o * 512 + 256 + c]);
}

// ---------------- mma.sync GEMM ----------------------------------------------
// MODE 1: BM=64,  BN=256, 256 thr (8 warps, 2Mx4N, warp tile 32x64), 2 CTAs/SM.
//         C = bf16(adj_f32) @ fT^T; fused row-sum -> inv_deg; epilogue scales,
//         writes bf16 neigh into g_A2[:, 768:1024].  A: 2-stage LDG->STS,
//         B: 3-stage cp.async per-tile groups, wait_group<1>.
// MODE 2: BM=128, BN=256, 512 thr (16 warps), 1 CTA/SM, 4-stage both operands.
//         C = A2 @ B2^T (K=1024 hi/lo split); epilogue writes fp32 out.
static constexpr int BN = 256, BK = 64;
static constexpr int BBYTES = BN * BK * 2;                   // 32 KB / stage

template <int MODE>
__global__ void __launch_bounds__((MODE == 1) ? 256 : 512, (MODE == 1) ? 2 : 1)
gemm_mma(float* __restrict__ outF, const float* __restrict__ adjF) {
    constexpr int  THREADS = (MODE == 1) ? 256 : 512;
    constexpr int  BMm     = (MODE == 1) ? 64  : 128;
    constexpr int  KT      = (MODE == 1) ? (NN / BK) : (K2 / BK);
    constexpr long ldb     = (MODE == 1) ? NN : K2;
    constexpr int  ASTG    = (MODE == 1) ? 2 : 4;
    constexpr int  BSTG    = (MODE == 1) ? 3 : 4;
    constexpr int  PREF    = (MODE == 1) ? 2 : 3;   // groups committed ahead
    constexpr int  ABYTES  = BMm * BK * 2;          // 8 KB / 16 KB
    constexpr uint32_t A_OFF = 0;
    constexpr uint32_t B_OFF = ASTG * ABYTES;
    const __nv_bfloat16* __restrict__ Bg = (MODE == 1) ? g_fT : g_B2;

    extern __shared__ char smraw[];
    __shared__ float sdeg[BMm];
    const uint32_t sb = (smem_u32(smraw) + 127u) & ~127u;

    const int tid  = threadIdx.x;
    const int lane = tid & 31;
    const int w    = tid >> 5;
    const int wm   = w >> 2;            // M dir: mode1 0..1, mode2 0..3
    const int wn   = w & 3;             // N dir: 0..3
    const long m0  = (long)blockIdx.x * BMm;

    float acc[2][8][4];
#pragma unroll
    for (int i = 0; i < 2; i++)
#pragma unroll
        for (int j = 0; j < 8; j++)
#pragma unroll
            for (int k = 0; k < 4; k++) acc[i][j][k] = 0.f;

    // --- B tile loader (cp.async, bf16, swizzled) ---
    auto cpB = [&](int s, int kt) {
        const long k0 = (long)kt * BK;
        const uint32_t base = sb + B_OFF + (uint32_t)s * BBYTES;
#pragma unroll
        for (int t = 0; t < BBYTES / 16 / THREADS; t++) {
            const int idx = tid + t * THREADS;
            const int row = idx >> 3, c = idx & 7;
            const uint32_t off = (uint32_t)row * 128u +
                                 ((uint32_t)(c ^ (row & 7)) << 4);
            cp16(base + off, Bg + (long)row * ldb + k0 + c * 8);
        }
    };
    // --- A tile loader, MODE2 (bf16 g_A2 via cp.async) ---
    auto cpA2 = [&](int s, int kt) {
        const long k0 = (long)kt * BK;
        const uint32_t base = sb + A_OFF + (uint32_t)s * ABYTES;
#pragma unroll
        for (int t = 0; t < ABYTES / 16 / THREADS; t++) {
            const int idx = tid + t * THREADS;
            const int row = idx >> 3, c = idx & 7;
            const uint32_t off = (uint32_t)row * 128u +
                                 ((uint32_t)(c ^ (row & 7)) << 4);
            cp16(base + off, g_A2 + (m0 + row) * (long)K2 + k0 + c * 8);
        }
    };

    // --- A tile register staging, MODE1 (f32 adj streaming LDG + row-sum) ---
    float4 rA[4];
    float  rowsum = 0.f;
    const int arow = tid >> 2;          // 0..BMm-1 (4 threads per row)
    const int aq   = tid & 3;           // quarter: cols aq*16 .. aq*16+15
    auto ldgA = [&](int kt) {
        const float* src = adjF + (m0 + arow) * (long)NN + (long)kt * BK + aq * 16;
#pragma unroll
        for (int j = 0; j < 4; j++) rA[j] = ldcs4(src + j * 4);
#pragma unroll
        for (int j = 0; j < 4; j++)
            rowsum += (rA[j].x + rA[j].y) + (rA[j].z + rA[j].w);
    };
    auto stsA = [&](int s) {
        const uint32_t base = sb + A_OFF + (uint32_t)s * ABYTES + (uint32_t)arow * 128u;
        const int rs = arow & 7;
#pragma unroll
        for (int j = 0; j < 2; j++) {
            const uint32_t p0 = packbf2(rA[2 * j].x, rA[2 * j].y);
            const uint32_t p1 = packbf2(rA[2 * j].z, rA[2 * j].w);
            const uint32_t p2 = packbf2(rA[2 * j + 1].x, rA[2 * j + 1].y);
            const uint32_t p3 = packbf2(rA[2 * j + 1].z, rA[2 * j + 1].w);
            sts128(base + ((uint32_t)((aq * 2 + j) ^ rs) << 4), p0, p1, p2, p3);
        }
    };

    // --- ldmatrix thread addressing (canonical m16n8k16 recipe) ---
    const int lhi  = lane >> 4;                       // k-chunk parity
    const int a_r0 = wm * 32 + (lane & 15);           // + mi*16
    const int b_r0 = wn * 64 + (lane & 15);           // + nb*16

    auto compute = [&](int sa, int sbg) {
        const uint32_t aBase = sb + A_OFF + (uint32_t)sa * ABYTES;
        const uint32_t bBase = sb + B_OFF + (uint32_t)sbg * BBYTES;
#pragma unroll
        for (int ks = 0; ks < 4; ks++) {              // 4 x k16 per BK=64
            uint32_t af[2][4], bf[4][4];
#pragma unroll
            for (int mi = 0; mi < 2; mi++) {
                const int row = a_r0 + mi * 16;
                const uint32_t addr = aBase + (uint32_t)row * 128u +
                    ((uint32_t)((ks * 2 + lhi) ^ (row & 7)) << 4);
                ldsm4(af[mi], addr);
            }
#pragma unroll
            for (int nb = 0; nb < 4; nb++) {
                const int row = b_r0 + nb * 16;
                const uint32_t addr = bBase + (uint32_t)row * 128u +
                    ((uint32_t)((ks * 2 + lhi) ^ (row & 7)) << 4);
                ldsm4(bf[nb], addr);
            }
#pragma unroll
            for (int mi = 0; mi < 2; mi++)
#pragma unroll
                for (int nb = 0; nb < 4; nb++) {
                    mma16816(acc[mi][nb * 2],     af[mi], bf[nb][0], bf[nb][2]);
                    mma16816(acc[mi][nb * 2 + 1], af[mi], bf[nb][1], bf[nb][3]);
                }
        }
    };

    // ---------------- prologue: commit PREF groups --------------------------
    if constexpr (MODE == 1) {
        ldgA(0); stsA(0);               // tile 0 A into stage 0
        ldgA(1);                        // tile 1 A staged in regs
        cpB(0, 0); cp_commit();
        cpB(1, 1); cp_commit();
    } else {
        cpA2(0, 0); cpB(0, 0); cp_commit();
        cpA2(1, 1); cpB(1, 1); cp_commit();
        cpA2(2, 2); cpB(2, 2); cp_commit();
    }

    // ---------------- main loop ----------------
    // Invariant at top of iter kt: committed groups = tiles {kt .. kt+PREF-1}.
    // wait<PREF-1> -> tile kt complete. Refill target stage (kt+PREF)%BSTG ==
    // (kt-1)%BSTG was read in compute(kt-1); the top barrier proves all warps
    // finished it.
    int sbi = 0;                        // stage of tile kt (kt % BSTG)
    for (int kt = 0; kt < KT; kt++) {
        cp_wait<PREF - 1>();
        __syncthreads();
        if (kt + PREF < KT) {
            int sn = sbi + PREF; if (sn >= BSTG) sn -= BSTG;
            if constexpr (MODE == 2) cpA2(sn, kt + PREF);
            cpB(sn, kt + PREF);
        }
        cp_commit();                    // exactly one group per iteration
        if constexpr (MODE == 1) {
            if (kt + 1 < KT) stsA((kt + 1) & 1);   // rA holds tile kt+1
            if (kt + 2 < KT) ldgA(kt + 2);
        }
        compute((MODE == 1) ? (kt & 1) : sbi, sbi);
        sbi++; if (sbi == BSTG) sbi = 0;
    }

    // ---------------- epilogue ----------------
    if constexpr (MODE == 1) {
        rowsum += __shfl_xor_sync(0xFFFFFFFFu, rowsum, 1);
        rowsum += __shfl_xor_sync(0xFFFFFFFFu, rowsum, 2);
        if ((tid & 3) == 0) sdeg[tid >> 2] = 1.0f / (rowsum + 1.0f);
        __syncthreads();
    }

#pragma unroll
    for (int mi = 0; mi < 2; mi++) {
        const int rl = wm * 32 + mi * 16 + (lane >> 2);
        const float slo = (MODE == 1) ? sdeg[rl]     : 1.f;
        const float shi = (MODE == 1) ? sdeg[rl + 8] : 1.f;
        const long glo = m0 + rl, ghi = glo + 8;
#pragma unroll
        for (int ni = 0; ni < 8; ni++) {
            const int col = wn * 64 + ni * 8 + (lane & 3) * 2;
            const float* a = acc[mi][ni];
            if constexpr (MODE == 1) {
                *reinterpret_cast<uint32_t*>(g_A2 + glo * K2 + 768 + col) =
                    packbf2(a[0] * slo, a[1] * slo);
                *reinterpret_cast<uint32_t*>(g_A2 + ghi * K2 + 768 + col) =
                    packbf2(a[2] * shi, a[3] * shi);
            } else {
                *reinterpret_cast<float2*>(outF + glo * DF + col) =
                    make_float2(a[0], a[1]);
                *reinterpret_cast<float2*>(outF + ghi * DF + col) =
                    make_float2(a[2], a[3]);
            }
        }
    }
}

static constexpr uint32_t SMEM1 = 2 * (64  * BK * 2) + 3 * BBYTES + 128; // ~112.1 KB
static constexpr uint32_t SMEM2 = 4 * (128 * BK * 2) + 4 * BBYTES + 128; // ~192.1 KB

// ---------------- launch -----------------------------------------------------
extern "C" void kernel_launch(void* const* d_in, const int* in_sizes, int n_in,
                              void* d_out, int out_size) {
    const float* features = nullptr;
    const float* adj      = nullptr;
    const float* W        = nullptr;
    for (int i = 0; i < n_in; i++) {
        if (in_sizes[i] == NN * DF)          features = (const float*)d_in[i];
        else if (in_sizes[i] == DF * 2 * DF) W        = (const float*)d_in[i];
        else                                  adj      = (const float*)d_in[i];
    }

    cudaFuncSetAttribute(gemm_mma<1>, cudaFuncAttributeMaxDynamicSharedMemorySize, SMEM1);
    cudaFuncSetAttribute(gemm_mma<2>, cudaFuncAttributeMaxDynamicSharedMemorySize, SMEM2);

    prep_fT<<<dim3(NN / 32, DF / 32), dim3(32, 8)>>>(features);
    prep_A2<<<NN, 256>>>(features);
    prep_W<<<DF, 256>>>(W);
    gemm_mma<1><<<NN / 64, 256, SMEM1>>>(nullptr, adj);
    gemm_mma<2><<<NN / 128, 512, SMEM2>>>((float*)d_out, nullptr);
}